// round 1
// baseline (speedup 1.0000x reference)
#include <cuda_runtime.h>

#define NRES 65536
#define KNB  16
#define HID  256      // 2*PAIR
#define LOC  128
#define FIN  130      // 64 rbf + 66 one-hot rows of w1

#define RBF_DC    (22.0f / 63.0f)     // center spacing, linspace(0,22,64)
#define RBF_INVS  (64.0f / 22.0f)     // 1/sigma, sigma = 22/64
#define GELU_C1   1.5957691216057308f // 2*sqrt(2/pi)
#define GELU_C2   0.07135481283f      // C1 * 0.044715

// Scratch: per-residue sum over valid edges of gelu(h)  [N, 256], plus valid count.
__device__ float g_hsum[(size_t)NRES * HID];
__device__ int   g_cnt[NRES];

// gelu(v) with tanh formulation, via sigmoid identity:
// gelu(v) = v * sigmoid(2u), u = sqrt(2/pi)(v + 0.044715 v^3)
__device__ __forceinline__ float gelu_tanh(float v) {
    float u2 = v * (GELU_C1 + GELU_C2 * v * v);   // = 2u
    float e  = __expf(u2);                        // inf/0 saturate correctly
    float r  = __fdividef(1.0f, 1.0f + e);        // e=inf -> 0, e=0 -> 1
    return v * (1.0f - r);                        // = v * sigmoid(2u)
}

// ---------------------------------------------------------------------------
// Kernel A: one warp per residue. Sparse GEMM1 (9 RBF rows + 1 one-hot row of
// w1 in smem) -> gelu -> accumulate over valid neighbours into g_hsum.
// Lane owns columns {4*lane .. 4*lane+3} and {128+4*lane .. 128+4*lane+3}
// (conflict-free LDS.128 / coalesced STG.128).
// ---------------------------------------------------------------------------
__global__ void __launch_bounds__(512, 1)
kA(const float* __restrict__ ca, const int* __restrict__ resi,
   const int* __restrict__ chain, const int* __restrict__ neigh,
   const float* __restrict__ w1, const float* __restrict__ b1)
{
    extern __shared__ float w1s[];   // [130][256] = 133120 B

    // cooperative load of w1 into smem
    {
        const float4* src = (const float4*)w1;
        float4* dst = (float4*)w1s;
        for (int idx = threadIdx.x; idx < FIN * HID / 4; idx += 512)
            dst[idx] = src[idx];
    }
    __syncthreads();

    const int lane = threadIdx.x & 31;
    const int wid  = threadIdx.x >> 5;
    const int i    = blockIdx.x * 16 + wid;

    const int colA = 4 * lane;
    const int colB = 128 + 4 * lane;

    // bias (zeros in this dataset, but honor it)
    const float4 b1a = *(const float4*)(b1 + colA);
    const float4 b1b = *(const float4*)(b1 + colB);

    const float cix = __ldg(ca + 3 * i + 0);
    const float ciy = __ldg(ca + 3 * i + 1);
    const float ciz = __ldg(ca + 3 * i + 2);
    const int   ri  = __ldg(resi + i);
    const int   chi = __ldg(chain + i);

    const int nb = __ldg(neigh + i * KNB + (lane & 15));

    float accA[4] = {0.f, 0.f, 0.f, 0.f};
    float accB[4] = {0.f, 0.f, 0.f, 0.f};
    int cnt = 0;

    #pragma unroll 1
    for (int k = 0; k < KNB; k++) {
        const int j = __shfl_sync(0xffffffffu, nb, k);
        if (j < 0) continue;          // warp-uniform
        cnt++;

        const float dx = cix - __ldg(ca + 3 * j + 0);
        const float dy = ciy - __ldg(ca + 3 * j + 1);
        const float dz = ciz - __ldg(ca + 3 * j + 2);
        const float d  = sqrtf(dx * dx + dy * dy + dz * dz);

        const int rj  = __ldg(resi + j);
        const int chj = __ldg(chain + j);
        int rd;
        if (chi != chj) rd = 65;
        else {
            int t = ri - rj;
            t = t < -32 ? -32 : (t > 32 ? 32 : t);
            rd = t + 32;
        }

        // init with one-hot row + bias
        const float* rowO = w1s + (64 + rd) * HID;
        float4 wa = *(const float4*)(rowO + colA);
        float4 wb = *(const float4*)(rowO + colB);
        float xA0 = b1a.x + wa.x, xA1 = b1a.y + wa.y, xA2 = b1a.z + wa.z, xA3 = b1a.w + wa.w;
        float xB0 = b1b.x + wb.x, xB1 = b1b.y + wb.y, xB2 = b1b.z + wb.z, xB3 = b1b.w + wb.w;

        // sparse RBF window: 9 bins around nearest center (others < 4e-6)
        int b0 = __float2int_rn(d * (1.0f / RBF_DC));
        b0 = b0 < 0 ? 0 : (b0 > 63 ? 63 : b0);
        #pragma unroll
        for (int t = 0; t < 9; t++) {
            const int b = b0 - 4 + t;
            if (b < 0 || b > 63) continue;
            const float z = (d - (float)b * RBF_DC) * RBF_INVS;
            const float e = __expf(-z * z);
            const float* row = w1s + b * HID;
            const float4 ra = *(const float4*)(row + colA);
            const float4 rb = *(const float4*)(row + colB);
            xA0 += e * ra.x; xA1 += e * ra.y; xA2 += e * ra.z; xA3 += e * ra.w;
            xB0 += e * rb.x; xB1 += e * rb.y; xB2 += e * rb.z; xB3 += e * rb.w;
        }

        accA[0] += gelu_tanh(xA0); accA[1] += gelu_tanh(xA1);
        accA[2] += gelu_tanh(xA2); accA[3] += gelu_tanh(xA3);
        accB[0] += gelu_tanh(xB0); accB[1] += gelu_tanh(xB1);
        accB[2] += gelu_tanh(xB2); accB[3] += gelu_tanh(xB3);
    }

    float* hout = g_hsum + (size_t)i * HID;
    *(float4*)(hout + colA) = make_float4(accA[0], accA[1], accA[2], accA[3]);
    *(float4*)(hout + colB) = make_float4(accB[0], accB[1], accB[2], accB[3]);
    if (lane == 0) g_cnt[i] = cnt;
}

// ---------------------------------------------------------------------------
// Kernel B: [64 x 256] hsum tile (smem) @ w2 [256 x 128] (smem), + cnt*b2,
// /K, fused LayerNorm (warp shuffle reduce), write out [64 x 128] fp32.
// Block = 256 threads = 8 warps; warp w handles residues w*8..w*8+7;
// lane owns output cols 4*lane..4*lane+3.
// ---------------------------------------------------------------------------
__global__ void __launch_bounds__(256, 1)
kB(const float* __restrict__ w2, const float* __restrict__ b2,
   const float* __restrict__ gamma, const float* __restrict__ beta,
   float* __restrict__ out)
{
    extern __shared__ float sm[];
    float* w2s = sm;                 // 256*128 = 32768 floats
    float* hs  = sm + 32768;         // 64*256  = 16384 floats
    float* cns = sm + 32768 + 16384; // 64 floats

    const int tid = threadIdx.x;
    {
        const float4* src = (const float4*)w2;
        float4* dst = (float4*)w2s;
        for (int idx = tid; idx < 32768 / 4; idx += 256)
            dst[idx] = src[idx];
    }
    const int base = blockIdx.x * 64;
    {
        const float4* src = (const float4*)(g_hsum + (size_t)base * HID);
        float4* dst = (float4*)hs;
        for (int idx = tid; idx < 16384 / 4; idx += 256)
            dst[idx] = src[idx];
    }
    if (tid < 64) cns[tid] = (float)g_cnt[base + tid];
    __syncthreads();

    const int lane = tid & 31;
    const int w    = tid >> 5;

    const float4 g4  = *(const float4*)(gamma + 4 * lane);
    const float4 be4 = *(const float4*)(beta  + 4 * lane);
    const float4 b24 = *(const float4*)(b2    + 4 * lane);

    float acc[8][4];
    #pragma unroll
    for (int r = 0; r < 8; r++)
        acc[r][0] = acc[r][1] = acc[r][2] = acc[r][3] = 0.0f;

    const float* hrow = hs + w * 8 * HID;

    for (int kk = 0; kk < HID; kk += 4) {
        float hv[8][4];
        #pragma unroll
        for (int r = 0; r < 8; r++) {
            const float4 t = *(const float4*)(hrow + r * HID + kk); // smem broadcast
            hv[r][0] = t.x; hv[r][1] = t.y; hv[r][2] = t.z; hv[r][3] = t.w;
        }
        #pragma unroll
        for (int q = 0; q < 4; q++) {
            const float4 wv = *(const float4*)(w2s + (kk + q) * LOC + 4 * lane);
            #pragma unroll
            for (int r = 0; r < 8; r++) {
                const float a = hv[r][q];
                acc[r][0] += a * wv.x;
                acc[r][1] += a * wv.y;
                acc[r][2] += a * wv.z;
                acc[r][3] += a * wv.w;
            }
        }
    }

    #pragma unroll
    for (int r = 0; r < 8; r++) {
        const int res = base + w * 8 + r;
        const float c = cns[w * 8 + r];
        const float inv_k = 1.0f / (float)KNB;
        float m0 = (acc[r][0] + c * b24.x) * inv_k;
        float m1 = (acc[r][1] + c * b24.y) * inv_k;
        float m2 = (acc[r][2] + c * b24.z) * inv_k;
        float m3 = (acc[r][3] + c * b24.w) * inv_k;

        float s  = m0 + m1 + m2 + m3;
        float s2 = m0 * m0 + m1 * m1 + m2 * m2 + m3 * m3;
        #pragma unroll
        for (int off = 16; off > 0; off >>= 1) {
            s  += __shfl_xor_sync(0xffffffffu, s,  off);
            s2 += __shfl_xor_sync(0xffffffffu, s2, off);
        }
        const float mu  = s * (1.0f / LOC);
        const float var = s2 * (1.0f / LOC) - mu * mu;
        const float rs  = rsqrtf(var + 1e-5f);

        float4 o;
        o.x = (m0 - mu) * rs * g4.x + be4.x;
        o.y = (m1 - mu) * rs * g4.y + be4.y;
        o.z = (m2 - mu) * rs * g4.z + be4.z;
        o.w = (m3 - mu) * rs * g4.w + be4.w;
        *(float4*)(out + (size_t)res * LOC + 4 * lane) = o;
    }
}

extern "C" void kernel_launch(void* const* d_in, const int* in_sizes, int n_in,
                              void* d_out, int out_size)
{
    const float* ca    = (const float*)d_in[0];
    const int*   resi  = (const int*)  d_in[1];
    const int*   chain = (const int*)  d_in[2];
    const int*   neigh = (const int*)  d_in[3];
    const float* w1    = (const float*)d_in[4];
    const float* b1    = (const float*)d_in[5];
    const float* w2    = (const float*)d_in[6];
    const float* b2    = (const float*)d_in[7];
    const float* gamma = (const float*)d_in[8];
    const float* beta  = (const float*)d_in[9];
    float* out = (float*)d_out;

    const int smA = FIN * HID * 4;                       // 133120 B
    const int smB = (32768 + 16384 + 64) * 4;            // 196864 B
    cudaFuncSetAttribute(kA, cudaFuncAttributeMaxDynamicSharedMemorySize, smA);
    cudaFuncSetAttribute(kB, cudaFuncAttributeMaxDynamicSharedMemorySize, smB);

    kA<<<NRES / 16, 512, smA>>>(ca, resi, chain, neigh, w1, b1);
    kB<<<NRES / 64, 256, smB>>>(w2, b2, gamma, beta, out);
}

// round 2
// speedup vs baseline: 1.2245x; 1.2245x over previous
#include <cuda_runtime.h>

#define NRES 65536
#define KNB  16
#define HID  256      // 2*PAIR
#define LOC  128
#define FIN  130      // 64 rbf + 66 one-hot rows of w1

#define RBF_DC    (22.0f / 63.0f)         // center spacing, linspace(0,22,64)
#define RBF_INVDC (63.0f / 22.0f)
#define RBF_INVS  (64.0f / 22.0f)         // 1/sigma, sigma = 22/64
#define DLT       (64.0f / 63.0f)         // bin spacing in sigma units
#define QCON      0.1269461f              // exp(-2*DLT*DLT)
#define FAR_D     23.2f                   // beyond last center + 3.5 sigma
#define GELU_C1   1.5957691216057308f     // 2*sqrt(2/pi)
#define GELU_C2   0.07135481283f          // C1 * 0.044715

// Scratch: per-residue sum over valid edges of gelu(h)  [N, 256], plus valid count.
__device__ float g_hsum[(size_t)NRES * HID];
__device__ int   g_cnt[NRES];

// gelu(v) tanh formulation via sigmoid identity: v * sigmoid(2u)
__device__ __forceinline__ float gelu_tanh(float v) {
    float u2 = v * (GELU_C1 + GELU_C2 * v * v);
    float e  = __expf(u2);
    float r  = __fdividef(1.0f, 1.0f + e);
    return v * (1.0f - r);
}

// ---------------------------------------------------------------------------
// Kernel A: one warp per residue. Sparse GEMM1 (<=7 RBF rows + 1 one-hot row)
// with w1 fp32 in smem -> gelu -> accumulate over valid neighbours.
// Far edges (d >= 23.2: all RBF bins negligible) use a precomputed
// G[rd] = gelu(w1_onehot[rd] + b1) table: 2 LDS + 8 FADD, no MUFU.
// ---------------------------------------------------------------------------
__global__ void __launch_bounds__(512, 1)
kA(const float* __restrict__ ca, const int* __restrict__ resi,
   const int* __restrict__ chain, const int* __restrict__ neigh,
   const float* __restrict__ w1, const float* __restrict__ b1)
{
    extern __shared__ float sm[];
    float* w1s = sm;                 // [130][256]
    float* G   = sm + FIN * HID;     // [66][256]

    // cooperative load of w1 into smem
    {
        const float4* src = (const float4*)w1;
        float4* dst = (float4*)w1s;
        for (int idx = threadIdx.x; idx < FIN * HID / 4; idx += 512)
            dst[idx] = src[idx];
    }
    __syncthreads();
    // build gelu table for pure-one-hot edges
    for (int idx = threadIdx.x; idx < 66 * HID; idx += 512) {
        const int c = idx & (HID - 1);
        G[idx] = gelu_tanh(w1s[64 * HID + idx] + __ldg(b1 + c));
    }
    __syncthreads();

    const int lane = threadIdx.x & 31;
    const int wid  = threadIdx.x >> 5;
    const int i    = blockIdx.x * 16 + wid;

    const int colA = 4 * lane;
    const int colB = 128 + 4 * lane;

    const float4 b1a = *(const float4*)(b1 + colA);
    const float4 b1b = *(const float4*)(b1 + colB);

    const float cix = __ldg(ca + 3 * i + 0);
    const float ciy = __ldg(ca + 3 * i + 1);
    const float ciz = __ldg(ca + 3 * i + 2);
    const int   ri  = __ldg(resi + i);
    const int   chi = __ldg(chain + i);

    const int nb = __ldg(neigh + i * KNB + (lane & 15));

    float accA[4] = {0.f, 0.f, 0.f, 0.f};
    float accB[4] = {0.f, 0.f, 0.f, 0.f};
    int cnt = 0;

    #pragma unroll 1
    for (int k = 0; k < KNB; k++) {
        const int j = __shfl_sync(0xffffffffu, nb, k);
        if (j < 0) continue;          // warp-uniform
        cnt++;

        const float dx = cix - __ldg(ca + 3 * j + 0);
        const float dy = ciy - __ldg(ca + 3 * j + 1);
        const float dz = ciz - __ldg(ca + 3 * j + 2);
        const float d  = sqrtf(dx * dx + dy * dy + dz * dz);

        const int rj  = __ldg(resi + j);
        const int chj = __ldg(chain + j);
        int rd;
        if (chi != chj) rd = 65;
        else {
            int t = ri - rj;
            t = t < -32 ? -32 : (t > 32 ? 32 : t);
            rd = t + 32;
        }

        if (d >= FAR_D) {
            // all RBF bins < 5e-6: h = G[rd]
            const float* g = G + rd * HID;
            const float4 ga = *(const float4*)(g + colA);
            const float4 gb = *(const float4*)(g + colB);
            accA[0] += ga.x; accA[1] += ga.y; accA[2] += ga.z; accA[3] += ga.w;
            accB[0] += gb.x; accB[1] += gb.y; accB[2] += gb.z; accB[3] += gb.w;
            continue;
        }

        // init with one-hot row + bias
        const float* rowO = w1s + (64 + rd) * HID;
        float4 wa = *(const float4*)(rowO + colA);
        float4 wb = *(const float4*)(rowO + colB);
        float xA0 = b1a.x + wa.x, xA1 = b1a.y + wa.y, xA2 = b1a.z + wa.z, xA3 = b1a.w + wa.w;
        float xB0 = b1b.x + wb.x, xB1 = b1b.y + wb.y, xB2 = b1b.z + wb.z, xB3 = b1b.w + wb.w;

        // 7-bin RBF window around nearest center; e_t via Gaussian recurrence
        int b0 = __float2int_rn(d * RBF_INVDC);
        b0 = b0 < 0 ? 0 : (b0 > 63 ? 63 : b0);
        const int bl   = b0 - 3 < 0 ? 0 : b0 - 3;
        const int tmax = 63 - bl;                     // rows above 63 masked
        float zl = (d - (float)bl * RBF_DC) * RBF_INVS;
        zl = zl > 30.0f ? 30.0f : zl;                 // keep m finite (e0 -> 0)
        float e = __expf(-zl * zl);
        float m = __expf(DLT * (2.0f * zl - DLT));

        const float* rowB = w1s + bl * HID;
        #pragma unroll
        for (int t = 0; t < 7; t++) {
            const float ee = (t <= tmax) ? e : 0.0f;
            const float4 ra = *(const float4*)(rowB + t * HID + colA);
            const float4 rb = *(const float4*)(rowB + t * HID + colB);
            xA0 += ee * ra.x; xA1 += ee * ra.y; xA2 += ee * ra.z; xA3 += ee * ra.w;
            xB0 += ee * rb.x; xB1 += ee * rb.y; xB2 += ee * rb.z; xB3 += ee * rb.w;
            e *= m; m *= QCON;
        }

        accA[0] += gelu_tanh(xA0); accA[1] += gelu_tanh(xA1);
        accA[2] += gelu_tanh(xA2); accA[3] += gelu_tanh(xA3);
        accB[0] += gelu_tanh(xB0); accB[1] += gelu_tanh(xB1);
        accB[2] += gelu_tanh(xB2); accB[3] += gelu_tanh(xB3);
    }

    float* hout = g_hsum + (size_t)i * HID;
    *(float4*)(hout + colA) = make_float4(accA[0], accA[1], accA[2], accA[3]);
    *(float4*)(hout + colB) = make_float4(accB[0], accB[1], accB[2], accB[3]);
    if (lane == 0) g_cnt[i] = cnt;
}

// ---------------------------------------------------------------------------
// Kernel B: 128 residues/block, 512 threads (16 warps), w2 fully resident in
// smem (128KB), hsum streamed in two 64KB K-chunks. Warp w -> residues
// w*8..w*8+7, lane -> output cols 4*lane..4*lane+3. Fused bias/mask/LN.
// ---------------------------------------------------------------------------
__global__ void __launch_bounds__(512, 1)
kB(const float* __restrict__ w2, const float* __restrict__ b2,
   const float* __restrict__ gamma, const float* __restrict__ beta,
   float* __restrict__ out)
{
    extern __shared__ float sm[];
    float* w2s = sm;                       // 256*128 = 32768 floats
    float* hs  = sm + 32768;               // 128*128 = 16384 floats
    float* cns = sm + 32768 + 16384;       // 128 floats

    const int tid  = threadIdx.x;
    const int base = blockIdx.x * 128;

    {
        const float4* src = (const float4*)w2;
        float4* dst = (float4*)w2s;
        for (int idx = tid; idx < 32768 / 4; idx += 512)
            dst[idx] = src[idx];
    }
    if (tid < 128) cns[tid] = (float)g_cnt[base + tid];

    const int lane = tid & 31;
    const int w    = tid >> 5;

    float acc[8][4];
    #pragma unroll
    for (int r = 0; r < 8; r++)
        acc[r][0] = acc[r][1] = acc[r][2] = acc[r][3] = 0.0f;

    #pragma unroll 1
    for (int p = 0; p < 2; p++) {
        __syncthreads();   // first iter: covers w2s/cns; later: hs readers done
        {
            float4* dst = (float4*)hs;
            for (int idx = tid; idx < 4096; idx += 512) {
                const int row = idx >> 5;
                const int c4  = idx & 31;
                dst[idx] = *(const float4*)(g_hsum + (size_t)(base + row) * HID + p * 128 + c4 * 4);
            }
        }
        __syncthreads();

        const float* hrow = hs + w * 8 * 128;
        const float* w2p  = w2s + p * 128 * LOC;
        for (int kk = 0; kk < 128; kk += 4) {
            float hv[8][4];
            #pragma unroll
            for (int r = 0; r < 8; r++) {
                const float4 t = *(const float4*)(hrow + r * 128 + kk);  // smem broadcast
                hv[r][0] = t.x; hv[r][1] = t.y; hv[r][2] = t.z; hv[r][3] = t.w;
            }
            #pragma unroll
            for (int q = 0; q < 4; q++) {
                const float4 wv = *(const float4*)(w2p + (kk + q) * LOC + 4 * lane);
                #pragma unroll
                for (int r = 0; r < 8; r++) {
                    const float a = hv[r][q];
                    acc[r][0] += a * wv.x;
                    acc[r][1] += a * wv.y;
                    acc[r][2] += a * wv.z;
                    acc[r][3] += a * wv.w;
                }
            }
        }
    }

    const float4 g4  = *(const float4*)(gamma + 4 * lane);
    const float4 be4 = *(const float4*)(beta  + 4 * lane);
    const float4 b24 = *(const float4*)(b2    + 4 * lane);

    #pragma unroll
    for (int r = 0; r < 8; r++) {
        const int res = base + w * 8 + r;
        const float c = cns[w * 8 + r];
        const float inv_k = 1.0f / (float)KNB;
        float m0 = (acc[r][0] + c * b24.x) * inv_k;
        float m1 = (acc[r][1] + c * b24.y) * inv_k;
        float m2 = (acc[r][2] + c * b24.z) * inv_k;
        float m3 = (acc[r][3] + c * b24.w) * inv_k;

        float s  = m0 + m1 + m2 + m3;
        float s2 = m0 * m0 + m1 * m1 + m2 * m2 + m3 * m3;
        #pragma unroll
        for (int off = 16; off > 0; off >>= 1) {
            s  += __shfl_xor_sync(0xffffffffu, s,  off);
            s2 += __shfl_xor_sync(0xffffffffu, s2, off);
        }
        const float mu  = s * (1.0f / LOC);
        const float var = s2 * (1.0f / LOC) - mu * mu;
        const float rs  = rsqrtf(var + 1e-5f);

        float4 o;
        o.x = (m0 - mu) * rs * g4.x + be4.x;
        o.y = (m1 - mu) * rs * g4.y + be4.y;
        o.z = (m2 - mu) * rs * g4.z + be4.z;
        o.w = (m3 - mu) * rs * g4.w + be4.w;
        *(float4*)(out + (size_t)res * LOC + 4 * lane) = o;
    }
}

extern "C" void kernel_launch(void* const* d_in, const int* in_sizes, int n_in,
                              void* d_out, int out_size)
{
    const float* ca    = (const float*)d_in[0];
    const int*   resi  = (const int*)  d_in[1];
    const int*   chain = (const int*)  d_in[2];
    const int*   neigh = (const int*)  d_in[3];
    const float* w1    = (const float*)d_in[4];
    const float* b1    = (const float*)d_in[5];
    const float* w2    = (const float*)d_in[6];
    const float* b2    = (const float*)d_in[7];
    const float* gamma = (const float*)d_in[8];
    const float* beta  = (const float*)d_in[9];
    float* out = (float*)d_out;

    const int smA = (FIN + 66) * HID * 4;                // 200704 B
    const int smB = (32768 + 16384 + 128) * 4;           // 197120 B
    cudaFuncSetAttribute(kA, cudaFuncAttributeMaxDynamicSharedMemorySize, smA);
    cudaFuncSetAttribute(kB, cudaFuncAttributeMaxDynamicSharedMemorySize, smB);

    kA<<<NRES / 16, 512, smA>>>(ca, resi, chain, neigh, w1, b1);
    kB<<<NRES / 64 / 2, 512, smB>>>(w2, b2, gamma, beta, out);
}

// round 3
// speedup vs baseline: 1.6637x; 1.3587x over previous
#include <cuda_runtime.h>

#define NRES 65536
#define KNB  16
#define HID  256      // 2*PAIR
#define LOC  128
#define FIN  130      // 64 rbf + 66 one-hot rows of w1

#define RBF_DC    (22.0f / 63.0f)         // center spacing, linspace(0,22,64)
#define RBF_INVDC (63.0f / 22.0f)
#define RBF_INVS  (64.0f / 22.0f)         // 1/sigma, sigma = 22/64
#define DLT       (64.0f / 63.0f)         // bin spacing in sigma units
#define QCON      0.1269461f              // exp(-2*DLT*DLT)
#define FAR_D     23.2f                   // last center + 3.5 sigma

// Scratch: per-residue sum over valid edges of gelu(h) [N,256], plus count.
__device__ float g_hsum[(size_t)NRES * HID];
__device__ int   g_cnt[NRES];

// gelu tanh-approx via HW MUFU.TANH (sm_75+), max abs err ~1.4e-5
__device__ __forceinline__ float gelu_t(float v) {
    float u = v * (0.7978845608f + 0.0356774081f * v * v);
    float t;
    asm("tanh.approx.f32 %0, %1;" : "=f"(t) : "f"(u));
    return 0.5f * v * (1.0f + t);
}

// ---------------------------------------------------------------------------
// Kernel A: one warp per residue. Edge metadata (d, rd, valid) precomputed
// per-lane with MLP=16, then a pure smem+FMA loop: sparse GEMM1
// (<=6 RBF rows + 1 one-hot row, w1 fp32 in smem) -> gelu -> accumulate.
// Far edges (d >= 23.2) use precomputed G[rd] = gelu(w1_onehot[rd]+b1).
// ---------------------------------------------------------------------------
__global__ void __launch_bounds__(512, 1)
kA(const float* __restrict__ ca, const int* __restrict__ resi,
   const int* __restrict__ chain, const int* __restrict__ neigh,
   const float* __restrict__ w1, const float* __restrict__ b1)
{
    extern __shared__ float sm[];
    float* w1s = sm;                 // [130][256]
    float* G   = sm + FIN * HID;     // [66][256]

    {
        const float4* src = (const float4*)w1;
        float4* dst = (float4*)w1s;
        for (int idx = threadIdx.x; idx < FIN * HID / 4; idx += 512)
            dst[idx] = src[idx];
    }
    __syncthreads();
    for (int idx = threadIdx.x; idx < 66 * HID; idx += 512) {
        const int c = idx & (HID - 1);
        G[idx] = gelu_t(w1s[64 * HID + idx] + __ldg(b1 + c));
    }
    __syncthreads();

    const int lane = threadIdx.x & 31;
    const int wid  = threadIdx.x >> 5;
    const int i    = blockIdx.x * 16 + wid;

    const int colA = 4 * lane;
    const int colB = 128 + 4 * lane;

    const float4 b1a = *(const float4*)(b1 + colA);
    const float4 b1b = *(const float4*)(b1 + colB);

    const float cix = __ldg(ca + 3 * i + 0);
    const float ciy = __ldg(ca + 3 * i + 1);
    const float ciz = __ldg(ca + 3 * i + 2);
    const int   ri  = __ldg(resi + i);
    const int   chi = __ldg(chain + i);

    // ---- per-lane edge precompute: lane (&15) owns edge lk ----
    const int lk = lane & 15;
    const int j0 = __ldg(neigh + i * KNB + lk);
    const bool valid = (j0 >= 0);
    const int  jj = valid ? j0 : 0;
    const float dx = cix - __ldg(ca + 3 * jj + 0);
    const float dy = ciy - __ldg(ca + 3 * jj + 1);
    const float dz = ciz - __ldg(ca + 3 * jj + 2);
    const float d_l = sqrtf(dx * dx + dy * dy + dz * dz);
    const int rj  = __ldg(resi + jj);
    const int chj = __ldg(chain + jj);
    int rd_l;
    if (chi != chj) rd_l = 65;
    else {
        int t = ri - rj;
        t = t < -32 ? -32 : (t > 32 ? 32 : t);
        rd_l = t + 32;
    }
    const unsigned vm = __ballot_sync(0xffffffffu, valid) & 0xffffu;

    float accA[4] = {0.f, 0.f, 0.f, 0.f};
    float accB[4] = {0.f, 0.f, 0.f, 0.f};

    #pragma unroll 1
    for (int k = 0; k < KNB; k++) {
        if (!((vm >> k) & 1)) continue;            // warp-uniform
        const float d  = __shfl_sync(0xffffffffu, d_l,  k);
        const int   rd = __shfl_sync(0xffffffffu, rd_l, k);

        if (d >= FAR_D) {                          // all RBF bins negligible
            const float* g = G + rd * HID;
            const float4 ga = *(const float4*)(g + colA);
            const float4 gb = *(const float4*)(g + colB);
            accA[0] += ga.x; accA[1] += ga.y; accA[2] += ga.z; accA[3] += ga.w;
            accB[0] += gb.x; accB[1] += gb.y; accB[2] += gb.z; accB[3] += gb.w;
            continue;
        }

        // init with one-hot row + bias
        const float* rowO = w1s + (64 + rd) * HID;
        float4 wa = *(const float4*)(rowO + colA);
        float4 wb = *(const float4*)(rowO + colB);
        float xA0 = b1a.x + wa.x, xA1 = b1a.y + wa.y, xA2 = b1a.z + wa.z, xA3 = b1a.w + wa.w;
        float xB0 = b1b.x + wb.x, xB1 = b1b.y + wb.y, xB2 = b1b.z + wb.z, xB3 = b1b.w + wb.w;

        // 6-bin RBF window [floor(x)-2 .. +3]; e_t via Gaussian recurrence.
        const float x = d * RBF_INVDC;
        int bl = (int)floorf(x) - 2;
        bl = bl < 0 ? 0 : bl;
        const int tmax = 63 - bl;
        const float zl = (d - (float)bl * RBF_DC) * RBF_INVS;   // <= ~3.1
        float e = __expf(-zl * zl);
        float m = __expf(DLT * (2.0f * zl - DLT));

        const float* rowB = w1s + bl * HID;
        #pragma unroll
        for (int t = 0; t < 6; t++) {
            const float ee = (t <= tmax) ? e : 0.0f;
            const float4 ra = *(const float4*)(rowB + t * HID + colA);
            const float4 rb = *(const float4*)(rowB + t * HID + colB);
            xA0 += ee * ra.x; xA1 += ee * ra.y; xA2 += ee * ra.z; xA3 += ee * ra.w;
            xB0 += ee * rb.x; xB1 += ee * rb.y; xB2 += ee * rb.z; xB3 += ee * rb.w;
            e *= m; m *= QCON;
        }

        accA[0] += gelu_t(xA0); accA[1] += gelu_t(xA1);
        accA[2] += gelu_t(xA2); accA[3] += gelu_t(xA3);
        accB[0] += gelu_t(xB0); accB[1] += gelu_t(xB1);
        accB[2] += gelu_t(xB2); accB[3] += gelu_t(xB3);
    }

    float* hout = g_hsum + (size_t)i * HID;
    *(float4*)(hout + colA) = make_float4(accA[0], accA[1], accA[2], accA[3]);
    *(float4*)(hout + colB) = make_float4(accB[0], accB[1], accB[2], accB[3]);
    if (lane == 0) g_cnt[i] = __popc(vm);
}

// ---------------------------------------------------------------------------
// Kernel B: 64 residues/block, 256 threads, K split in 2 phases; per phase a
// 128x128 w2 tile (64KB) + 64x128 hs tile (32KB) live in smem -> 96KB/block
// -> 2 blocks/SM. Warp w -> residues w*8..w*8+7, lane -> cols 4*lane..+3.
// Fused cnt*b2, /K, LayerNorm (warp shuffle).
// ---------------------------------------------------------------------------
__global__ void __launch_bounds__(256, 2)
kB(const float* __restrict__ w2, const float* __restrict__ b2,
   const float* __restrict__ gamma, const float* __restrict__ beta,
   float* __restrict__ out)
{
    extern __shared__ float sm[];
    float* w2s = sm;                       // 128*128 = 16384 floats (phase tile)
    float* hs  = sm + 16384;               // 64*128  = 8192 floats
    float* cns = sm + 16384 + 8192;        // 64 floats

    const int tid  = threadIdx.x;
    const int base = blockIdx.x * 64;
    const int lane = tid & 31;
    const int w    = tid >> 5;

    float acc[8][4];
    #pragma unroll
    for (int r = 0; r < 8; r++)
        acc[r][0] = acc[r][1] = acc[r][2] = acc[r][3] = 0.0f;

    #pragma unroll 1
    for (int p = 0; p < 2; p++) {
        __syncthreads();   // readers of previous phase done
        {
            const float4* src = (const float4*)(w2 + p * 128 * LOC);
            float4* dst = (float4*)w2s;
            for (int idx = tid; idx < 4096; idx += 256)
                dst[idx] = src[idx];
        }
        {
            float4* dst = (float4*)hs;
            for (int idx = tid; idx < 2048; idx += 256) {
                const int row = idx >> 5;
                const int c4  = idx & 31;
                dst[idx] = *(const float4*)(g_hsum + (size_t)(base + row) * HID + p * 128 + c4 * 4);
            }
        }
        if (p == 0 && tid < 64) cns[tid] = (float)g_cnt[base + tid];
        __syncthreads();

        const float* hrow = hs + w * 8 * 128;
        for (int kk = 0; kk < 128; kk += 4) {
            float hv[8][4];
            #pragma unroll
            for (int r = 0; r < 8; r++) {
                const float4 t = *(const float4*)(hrow + r * 128 + kk);  // smem broadcast
                hv[r][0] = t.x; hv[r][1] = t.y; hv[r][2] = t.z; hv[r][3] = t.w;
            }
            #pragma unroll
            for (int q = 0; q < 4; q++) {
                const float4 wv = *(const float4*)(w2s + (kk + q) * LOC + 4 * lane);
                #pragma unroll
                for (int r = 0; r < 8; r++) {
                    const float a = hv[r][q];
                    acc[r][0] += a * wv.x;
                    acc[r][1] += a * wv.y;
                    acc[r][2] += a * wv.z;
                    acc[r][3] += a * wv.w;
                }
            }
        }
    }

    const float4 g4  = *(const float4*)(gamma + 4 * lane);
    const float4 be4 = *(const float4*)(beta  + 4 * lane);
    const float4 b24 = *(const float4*)(b2    + 4 * lane);

    #pragma unroll
    for (int r = 0; r < 8; r++) {
        const int res = base + w * 8 + r;
        const float c = cns[w * 8 + r];
        const float inv_k = 1.0f / (float)KNB;
        float m0 = (acc[r][0] + c * b24.x) * inv_k;
        float m1 = (acc[r][1] + c * b24.y) * inv_k;
        float m2 = (acc[r][2] + c * b24.z) * inv_k;
        float m3 = (acc[r][3] + c * b24.w) * inv_k;

        float s  = m0 + m1 + m2 + m3;
        float s2 = m0 * m0 + m1 * m1 + m2 * m2 + m3 * m3;
        #pragma unroll
        for (int off = 16; off > 0; off >>= 1) {
            s  += __shfl_xor_sync(0xffffffffu, s,  off);
            s2 += __shfl_xor_sync(0xffffffffu, s2, off);
        }
        const float mu  = s * (1.0f / LOC);
        const float var = s2 * (1.0f / LOC) - mu * mu;
        const float rs  = rsqrtf(var + 1e-5f);

        float4 o;
        o.x = (m0 - mu) * rs * g4.x + be4.x;
        o.y = (m1 - mu) * rs * g4.y + be4.y;
        o.z = (m2 - mu) * rs * g4.z + be4.z;
        o.w = (m3 - mu) * rs * g4.w + be4.w;
        *(float4*)(out + (size_t)res * LOC + 4 * lane) = o;
    }
}

extern "C" void kernel_launch(void* const* d_in, const int* in_sizes, int n_in,
                              void* d_out, int out_size)
{
    const float* ca    = (const float*)d_in[0];
    const int*   resi  = (const int*)  d_in[1];
    const int*   chain = (const int*)  d_in[2];
    const int*   neigh = (const int*)  d_in[3];
    const float* w1    = (const float*)d_in[4];
    const float* b1    = (const float*)d_in[5];
    const float* w2    = (const float*)d_in[6];
    const float* b2    = (const float*)d_in[7];
    const float* gamma = (const float*)d_in[8];
    const float* beta  = (const float*)d_in[9];
    float* out = (float*)d_out;

    const int smA = (FIN + 66) * HID * 4;                // 200704 B
    const int smB = (16384 + 8192 + 64) * 4;             // 98560 B
    cudaFuncSetAttribute(kA, cudaFuncAttributeMaxDynamicSharedMemorySize, smA);
    cudaFuncSetAttribute(kB, cudaFuncAttributeMaxDynamicSharedMemorySize, smB);

    kA<<<NRES / 16, 512, smA>>>(ca, resi, chain, neigh, w1, b1);
    kB<<<NRES / 64, 256, smB>>>(w2, b2, gamma, beta, out);
}